// round 10
// baseline (speedup 1.0000x reference)
#include <cuda_runtime.h>
#include <cuda_fp16.h>

#define NN 100000
#define EE 1600000
#define FIN 100
#define D 64
#define GG 500
#define SCAN_T 512
#define SCAN_NB ((NN + SCAN_T - 1) / SCAN_T)
#define APAD 132

// ---------------- scratch (device globals; no allocs allowed) ----------------
__device__ float g_deg[NN];
__device__ int   g_cntn[NN];
__device__ int   g_ptr[NN + 1];
__device__ int   g_partials[SCAN_NB];
__device__ int2  g_csr[EE];        // packed {row, norm_bits}
__device__ float g_out0[NN * D];
__device__ uint4 g_hA[NN * 8];     // h fp16 ping: 64 halves = 8 uint4 per row
__device__ uint4 g_hB[NN * 8];     // h fp16 pong
__device__ float g_sums[GG * D];
__device__ float g_cnt[GG];
__device__ int g_is64_edge;
__device__ int g_is64_batch;

__device__ __forceinline__ int load_idx(const void* p, long long i, int is64) {
    return is64 ? (int)((const long long*)p)[i] : ((const int*)p)[i];
}

// ptr fixup inlined: final ptr(n) = g_ptr[n] + partials[n>>9]
__device__ __forceinline__ int ptr_of(int n) {
    return (n == NN) ? EE : g_ptr[n] + g_partials[n >> 9];
}

// ---------------- init: zero scratch + dtype detect (one kernel) -------------
__global__ void init_kernel(const int* ei, const int* bat) {
    int t = blockIdx.x * 256 + threadIdx.x;
    if (t < NN) { g_deg[t] = 0.f; g_cntn[t] = 0; }
    if (t < GG * D) g_sums[t] = 0.f;
    if (t < GG) g_cnt[t] = 0.f;
    if (blockIdx.x == 0 && threadIdx.x < 32) {
        int i = threadIdx.x;
        int nz_e = 0, nz_b = 0;
        for (int j = i; j < 128; j += 32) {
            int w = 1 + 700 * j;  // always odd, < NN words
            nz_e |= (ei[w] != 0);
            nz_b |= (bat[w] != 0);
        }
        unsigned be = __ballot_sync(0xffffffffu, nz_e);
        unsigned bb = __ballot_sync(0xffffffffu, nz_b);
        if (i == 0) {
            g_is64_edge = (be == 0);
            g_is64_batch = (bb == 0);
        }
    }
}

// ---------------- fused: lin0 GEMM (fp32, R7 schedule) + degree histogram ----
__global__ void fused_lin0_deg(const float* __restrict__ A, const float* __restrict__ W,
                               const float* __restrict__ biasC, float* __restrict__ C,
                               const void* ei, const float* __restrict__ ew,
                               int gemm_blocks) {
    __shared__ float Ws[FIN * D];
    __shared__ float As[20 * APAD];
    int tid = threadIdx.x;

    if (blockIdx.x >= gemm_blocks) {
        int e = (blockIdx.x - gemm_blocks) * 256 + tid;
        if (e < EE) {
            int c = load_idx(ei, (long long)EE + e, g_is64_edge);
            atomicAdd(&g_deg[c], ew[e]);
            atomicAdd(&g_cntn[c], 1);
        }
        return;
    }

    int row0 = blockIdx.x * 128;
    for (int i = tid; i < FIN * D; i += 256) Ws[i] = W[i];
    int tx = tid & 15, ty = tid >> 4;
    float acc[8][4] = {};

    for (int kb = 0; kb < FIN; kb += 20) {
        __syncthreads();  // also guards Ws on first iteration
        for (int i = tid; i < 128 * 20; i += 256) {
            int rr = i / 20, kk = i - rr * 20;
            int r = row0 + rr;
            As[kk * APAD + rr] = (r < NN) ? A[(long long)r * FIN + kb + kk] : 0.f;
        }
        __syncthreads();
#pragma unroll
        for (int k = 0; k < 20; k++) {
            float4 a0 = *(const float4*)&As[k * APAD + ty * 8];
            float4 a1 = *(const float4*)&As[k * APAD + ty * 8 + 4];
            float4 wv = *(const float4*)&Ws[(kb + k) * D + tx * 4];
            float av[8] = {a0.x, a0.y, a0.z, a0.w, a1.x, a1.y, a1.z, a1.w};
#pragma unroll
            for (int i2 = 0; i2 < 8; i2++) {
                acc[i2][0] += av[i2] * wv.x;
                acc[i2][1] += av[i2] * wv.y;
                acc[i2][2] += av[i2] * wv.z;
                acc[i2][3] += av[i2] * wv.w;
            }
        }
    }
    int c0 = tx * 4;
    float4 bc = *(const float4*)&biasC[c0];
#pragma unroll
    for (int i2 = 0; i2 < 8; i2++) {
        int r = row0 + ty * 8 + i2;
        if (r >= NN) break;
        float4 v = make_float4(fmaxf(acc[i2][0] + bc.x, 0.f), fmaxf(acc[i2][1] + bc.y, 0.f),
                               fmaxf(acc[i2][2] + bc.z, 0.f), fmaxf(acc[i2][3] + bc.w, 0.f));
        *(float4*)&C[(long long)r * D + c0] = v;
    }
}

// ---------------- two-level exclusive scan over g_cntn -> g_ptr --------------
__global__ void scan1_kernel() {
    __shared__ int sh[SCAN_T];
    int tid = threadIdx.x;
    int i = blockIdx.x * SCAN_T + tid;
    int v = (i < NN) ? g_cntn[i] : 0;
    sh[tid] = v;
    __syncthreads();
    for (int off = 1; off < SCAN_T; off <<= 1) {
        int t = (tid >= off) ? sh[tid - off] : 0;
        __syncthreads();
        sh[tid] += t;
        __syncthreads();
    }
    if (i < NN) g_ptr[i] = sh[tid] - v;  // exclusive (local)
    if (tid == SCAN_T - 1) g_partials[blockIdx.x] = sh[tid];
}

__global__ void scan2_kernel() {  // 1 block of 256 (SCAN_NB=196 < 256)
    __shared__ int sh[256];
    int tid = threadIdx.x;
    int v = (tid < SCAN_NB) ? g_partials[tid] : 0;
    sh[tid] = v;
    __syncthreads();
    for (int off = 1; off < 256; off <<= 1) {
        int t = (tid >= off) ? sh[tid - off] : 0;
        __syncthreads();
        sh[tid] += t;
        __syncthreads();
    }
    if (tid < SCAN_NB) g_partials[tid] = sh[tid] - v;  // exclusive
}

// ---------------- conv-0 GEMM (fp32, R7 schedule, fp16 out) + CSR scatter ----
__global__ void gemm_conv0(const float* __restrict__ A, const float* __restrict__ W,
                           unsigned* __restrict__ hout,
                           const void* ei, const float* __restrict__ ew,
                           int gemm_blocks) {
    __shared__ float Ws[D * D];
    __shared__ float As[32 * APAD];

    int tid = threadIdx.x;
    if (blockIdx.x >= gemm_blocks) {
        int e = (blockIdx.x - gemm_blocks) * 256 + tid;
        if (e < EE) {
            int is64 = g_is64_edge;
            int r = load_idx(ei, e, is64);
            int c = load_idx(ei, (long long)EE + e, is64);
            float dr = g_deg[r], dc = g_deg[c];
            float ir = dr > 0.f ? rsqrtf(dr) : 0.f;
            float ic = dc > 0.f ? rsqrtf(dc) : 0.f;
            int old = atomicSub(&g_cntn[c], 1);
            int p = ptr_of(c) + old - 1;
            g_csr[p] = make_int2(r, __float_as_int(ir * ew[e] * ic));
        }
        return;
    }

    int row0 = blockIdx.x * 128;
    for (int i = tid; i < D * D; i += 256) Ws[i] = W[i];
    int tx = tid & 15, ty = tid >> 4;
    float acc[8][4] = {};

    for (int kb = 0; kb < D; kb += 32) {
        __syncthreads();
        for (int i = tid; i < 128 * 32; i += 256) {
            int rr = i >> 5, kk = i & 31;
            int r = row0 + rr;
            As[kk * APAD + rr] = (r < NN) ? A[(long long)r * D + kb + kk] : 0.f;
        }
        __syncthreads();
#pragma unroll
        for (int k = 0; k < 32; k++) {
            float4 a0 = *(const float4*)&As[k * APAD + ty * 8];
            float4 a1 = *(const float4*)&As[k * APAD + ty * 8 + 4];
            float4 wv = *(const float4*)&Ws[(kb + k) * D + tx * 4];
            float av[8] = {a0.x, a0.y, a0.z, a0.w, a1.x, a1.y, a1.z, a1.w};
#pragma unroll
            for (int i2 = 0; i2 < 8; i2++) {
                acc[i2][0] += av[i2] * wv.x;
                acc[i2][1] += av[i2] * wv.y;
                acc[i2][2] += av[i2] * wv.z;
                acc[i2][3] += av[i2] * wv.w;
            }
        }
    }

#pragma unroll
    for (int i2 = 0; i2 < 8; i2++) {
        int r = row0 + ty * 8 + i2;
        if (r >= NN) break;
        __half2 ha = __floats2half2_rn(acc[i2][0], acc[i2][1]);
        __half2 hb = __floats2half2_rn(acc[i2][2], acc[i2][3]);
        uint2 u;
        u.x = *(unsigned*)&ha;
        u.y = *(unsigned*)&hb;
        ((uint2*)hout)[(long long)r * 16 + tx] = u;
    }
}

// ---------------- CSR aggregation core (fp16 gather, packed csr) -------------
// One warp per node; 4 edges in flight (q=lane>>3), 8 lanes x uint4 = 128B row.
// After xor-reductions, EVERY lane holds acc[c] = agg col (8*(lane&7)+c).
__device__ __forceinline__ void agg_core(int node, const uint4* __restrict__ h,
                                         int q, int p, float acc[8]) {
    int s = ptr_of(node), e = ptr_of(node + 1);
    for (int i = s + q; i < e; i += 4) {
        int2 ed = g_csr[i];
        float nv = __int_as_float(ed.y);
        uint4 u = h[ed.x * 8 + p];
        __half2* hh = (__half2*)&u;
#pragma unroll
        for (int c = 0; c < 4; c++) {
            float2 f = __half22float2(hh[c]);
            acc[2 * c]     += f.x * nv;
            acc[2 * c + 1] += f.y * nv;
        }
    }
#pragma unroll
    for (int c = 0; c < 8; c++) {
        acc[c] += __shfl_xor_sync(0xffffffffu, acc[c], 8);
        acc[c] += __shfl_xor_sync(0xffffffffu, acc[c], 16);
    }
}

// ---------------- fused: agg (128 nodes -> smem) + tiled GEMM -> fp16 h ------
// Phase 1: 8 warps x 16 nodes; out = relu(agg+bias) into As[k][node] (fp32,
// XOR-swizzled groups-of-4 so the 8-lane column scatter is conflict-free).
// Phase 2: 256-thread tiled GEMM: h_next[128,64] = As^T @ W, fp16 out.
__global__ void agg_gemm(const uint4* __restrict__ hin,
                         const float* __restrict__ bias,
                         const float* __restrict__ Wn,
                         unsigned* __restrict__ hout) {
    __shared__ float Ws[D * D];     // 16 KB
    __shared__ float As[D * 128];   // 32 KB, [k][node] swizzled
    int tid = threadIdx.x;
    for (int i = tid; i < D * D; i += 256) Ws[i] = Wn[i];

    int warp = tid >> 5, lane = tid & 31;
    int q = lane >> 3, p = lane & 7;
    float bv[8];
#pragma unroll
    for (int j = 0; j < 8; j++) bv[j] = __ldg(&bias[8 * p + j]);

    int nbase = blockIdx.x * 128 + warp * 16;
    for (int it = 0; it < 16; it++) {
        int node = nbase + it;
        float acc[8] = {};
        if (node < NN) agg_core(node, hin, q, p, acc);
        if (q == 0) {
            int nloc = warp * 16 + it;         // 0..127
            int g = nloc >> 2, o = nloc & 3;
#pragma unroll
            for (int j = 0; j < 8; j++) {
                int c = 8 * p + j;
                float v = (node < NN) ? fmaxf(acc[j] + bv[j], 0.f) : 0.f;
                As[c * 128 + ((g ^ ((c >> 3) & 7)) << 2) + o] = v;
            }
        }
    }
    __syncthreads();

    // phase 2: txg = col group (8 cols), tyg = node group (4 nodes)
    int txg = tid & 7, tyg = tid >> 3;
    float acc2[4][8] = {};
#pragma unroll
    for (int k = 0; k < D; k++) {
        int key = (k >> 3) & 7;
        float4 a = *(const float4*)&As[k * 128 + ((tyg ^ key) << 2)];
        float4 w0 = *(const float4*)&Ws[k * D + txg * 8];
        float4 w1 = *(const float4*)&Ws[k * D + txg * 8 + 4];
        float av[4] = {a.x, a.y, a.z, a.w};
        float wv[8] = {w0.x, w0.y, w0.z, w0.w, w1.x, w1.y, w1.z, w1.w};
#pragma unroll
        for (int i2 = 0; i2 < 4; i2++)
#pragma unroll
            for (int j2 = 0; j2 < 8; j2++)
                acc2[i2][j2] += av[i2] * wv[j2];
    }
#pragma unroll
    for (int i2 = 0; i2 < 4; i2++) {
        int r = blockIdx.x * 128 + tyg * 4 + i2;
        if (r >= NN) break;
        __half2 h0 = __floats2half2_rn(acc2[i2][0], acc2[i2][1]);
        __half2 h1 = __floats2half2_rn(acc2[i2][2], acc2[i2][3]);
        __half2 h2 = __floats2half2_rn(acc2[i2][4], acc2[i2][5]);
        __half2 h3 = __floats2half2_rn(acc2[i2][6], acc2[i2][7]);
        uint4 u;
        u.x = *(unsigned*)&h0;
        u.y = *(unsigned*)&h1;
        u.z = *(unsigned*)&h2;
        u.w = *(unsigned*)&h3;
        *(uint4*)&hout[(long long)r * 32 + txg * 4] = u;
    }
}

__device__ __forceinline__ void red_add_v4(float4* addr, float4 v) {
    asm volatile("red.global.add.v4.f32 [%0], {%1,%2,%3,%4};"
                 :: "l"(addr), "f"(v.x), "f"(v.y), "f"(v.z), "f"(v.w)
                 : "memory");
}

// Last layer: aggregate + bias + relu + mean-pool accumulate.
__global__ void agg_pool(const uint4* __restrict__ h,
                         const float* __restrict__ bias, const void* batch) {
    int node = (blockIdx.x * blockDim.x + threadIdx.x) >> 5;
    if (node >= NN) return;
    int lane = threadIdx.x & 31;
    int q = lane >> 3, p = lane & 7;
    float acc[8] = {};
    agg_core(node, h, q, p, acc);
    if (q == 0) {
        int g = load_idx(batch, node, g_is64_batch);
        float4 b0 = *(const float4*)&bias[8 * p];
        float4 b1 = *(const float4*)&bias[8 * p + 4];
        float4 o0 = make_float4(fmaxf(acc[0] + b0.x, 0.f), fmaxf(acc[1] + b0.y, 0.f),
                                fmaxf(acc[2] + b0.z, 0.f), fmaxf(acc[3] + b0.w, 0.f));
        float4 o1 = make_float4(fmaxf(acc[4] + b1.x, 0.f), fmaxf(acc[5] + b1.y, 0.f),
                                fmaxf(acc[6] + b1.z, 0.f), fmaxf(acc[7] + b1.w, 0.f));
        float* row = g_sums + g * D + 8 * p;
        red_add_v4((float4*)row, o0);
        red_add_v4((float4*)(row + 4), o1);
        if (p == 0) atomicAdd(&g_cnt[g], 1.0f);
    }
}

// ---------------- fused MLP tail: lin1 -> fc0 -> fc1 -> lin2 ----------------
__global__ void tail_kernel(const float* __restrict__ W1, const float* __restrict__ b1,
                            const float* __restrict__ fcw, const float* __restrict__ fcb,
                            const float* __restrict__ w2, const float* __restrict__ b2,
                            float* __restrict__ out) {
    int g = blockIdx.x, tid = threadIdx.x;  // 64 threads
    __shared__ float buf[2][64];
    __shared__ float red[64];

    buf[0][tid] = g_sums[g * D + tid] / fmaxf(g_cnt[g], 1.f);
    __syncthreads();
    {
        float acc = 0.f;
#pragma unroll
        for (int k = 0; k < 64; k++) acc += buf[0][k] * W1[k * D + tid];
        buf[1][tid] = fmaxf(acc + b1[tid], 0.f);
        __syncthreads();
    }
    int cur = 1;
    for (int L = 0; L < 2; L++) {
        const float* W = fcw + L * D * D;
        float acc = 0.f;
#pragma unroll
        for (int k = 0; k < 64; k++) acc += buf[cur][k] * W[k * D + tid];
        __syncthreads();
        buf[cur ^ 1][tid] = fmaxf(acc + fcb[L * D + tid], 0.f);
        cur ^= 1;
        __syncthreads();
    }
    red[tid] = buf[cur][tid] * w2[tid];
    __syncthreads();
    if (tid < 32) {
        float s = red[tid] + red[tid + 32];
#pragma unroll
        for (int off = 16; off; off >>= 1) s += __shfl_down_sync(0xffffffffu, s, off);
        if (tid == 0) out[g] = s + b2[0];
    }
}

// ---------------- launch ----------------
extern "C" void kernel_launch(void* const* d_in, const int* in_sizes, int n_in,
                              void* d_out, int out_size) {
    const float* x      = (const float*)d_in[0];
    const void*  ei     = d_in[1];
    const float* ew     = (const float*)d_in[2];
    const void*  batch  = d_in[3];
    const float* lin0_w = (const float*)d_in[4];
    const float* lin0_b = (const float*)d_in[5];
    const float* conv_w = (const float*)d_in[6];
    const float* conv_b = (const float*)d_in[7];
    const float* lin1_w = (const float*)d_in[8];
    const float* lin1_b = (const float*)d_in[9];
    const float* fc_w   = (const float*)d_in[10];
    const float* fc_b   = (const float*)d_in[11];
    const float* lin2_w = (const float*)d_in[12];
    const float* lin2_b = (const float*)d_in[13];
    float* out = (float*)d_out;

    float* p_out0;
    uint4 *p_hA, *p_hB;
    cudaGetSymbolAddress((void**)&p_out0, g_out0);
    cudaGetSymbolAddress((void**)&p_hA, g_hA);
    cudaGetSymbolAddress((void**)&p_hB, g_hB);

    // init: zero deg/cntn/sums/cnt + dtype detect
    init_kernel<<<(NN + 255) / 256, 256>>>((const int*)ei, (const int*)batch);

    // fused lin0 GEMM + degree histogram (overlapped)
    const int GB = (NN + 127) / 128;           // 782 gemm blocks
    const int DB = (EE + 255) / 256;           // 6250 edge blocks
    fused_lin0_deg<<<GB + DB, 256>>>(x, lin0_w, lin0_b, p_out0, ei, ew, GB);

    scan1_kernel<<<SCAN_NB, SCAN_T>>>();
    scan2_kernel<<<1, 256>>>();

    // conv-0 GEMM (out0 -> hA) fused with CSR scatter (overlapped)
    gemm_conv0<<<GB + DB, 256>>>(p_out0, conv_w, (unsigned*)p_hA, ei, ew, GB);

    // layers 1..3: fused agg + bias/relu + next conv GEMM (smem tile)
    agg_gemm<<<GB, 256>>>(p_hA, conv_b + 0 * D, conv_w + 1 * D * D, (unsigned*)p_hB);
    agg_gemm<<<GB, 256>>>(p_hB, conv_b + 1 * D, conv_w + 2 * D * D, (unsigned*)p_hA);
    agg_gemm<<<GB, 256>>>(p_hA, conv_b + 2 * D, conv_w + 3 * D * D, (unsigned*)p_hB);

    // last layer: agg + bias/relu + mean-pool
    const int AGB = (NN * 32) / 256;  // 12500 blocks
    agg_pool<<<AGB, 256>>>(p_hB, conv_b + 3 * D, batch);

    tail_kernel<<<GG, 64>>>(lin1_w, lin1_b, fc_w, fc_b, lin2_w, lin2_b, out);
}

// round 11
// speedup vs baseline: 1.1709x; 1.1709x over previous
#include <cuda_runtime.h>
#include <cuda_fp16.h>

#define NN 100000
#define EE 1600000
#define FIN 100
#define D 64
#define GG 500
#define SCAN_T 512
#define SCAN_NB ((NN + SCAN_T - 1) / SCAN_T)
#define APAD 132

// ---------------- scratch (device globals; no allocs allowed) ----------------
__device__ float g_deg[NN];
__device__ int   g_cntn[NN];
__device__ int   g_ptr[NN + 1];
__device__ int   g_partials[SCAN_NB];
__device__ int2  g_csr[EE];        // packed {row, norm_bits}
__device__ float g_out0[NN * D];
__device__ uint4 g_hh[NN * 8];     // h fp16: 64 halves = 8 uint4 per row
__device__ float g_aggA[NN * D];
__device__ float g_aggB[NN * D];
__device__ float g_sums[GG * D];
__device__ float g_cnt[GG];
__device__ int g_is64_edge;
__device__ int g_is64_batch;

__device__ __forceinline__ int load_idx(const void* p, long long i, int is64) {
    return is64 ? (int)((const long long*)p)[i] : ((const int*)p)[i];
}

// ptr fixup inlined: final ptr(n) = g_ptr[n] + partials[n>>9]
__device__ __forceinline__ int ptr_of(int n) {
    return (n == NN) ? EE : g_ptr[n] + g_partials[n >> 9];
}

// ---------------- init: zero scratch + dtype detect (one kernel) -------------
__global__ void init_kernel(const int* ei, const int* bat) {
    int t = blockIdx.x * 256 + threadIdx.x;
    if (t < NN) { g_deg[t] = 0.f; g_cntn[t] = 0; }
    if (t < GG * D) g_sums[t] = 0.f;
    if (t < GG) g_cnt[t] = 0.f;
    if (blockIdx.x == 0 && threadIdx.x < 32) {
        int i = threadIdx.x;
        int nz_e = 0, nz_b = 0;
        for (int j = i; j < 128; j += 32) {
            int w = 1 + 700 * j;  // always odd, < NN words
            nz_e |= (ei[w] != 0);
            nz_b |= (bat[w] != 0);
        }
        unsigned be = __ballot_sync(0xffffffffu, nz_e);
        unsigned bb = __ballot_sync(0xffffffffu, nz_b);
        if (i == 0) {
            g_is64_edge = (be == 0);
            g_is64_batch = (bb == 0);
        }
    }
}

// ---------------- fused: lin0 GEMM (fp32, R7 schedule) + degree histogram ----
__global__ void fused_lin0_deg(const float* __restrict__ A, const float* __restrict__ W,
                               const float* __restrict__ biasC, float* __restrict__ C,
                               const void* ei, const float* __restrict__ ew,
                               int gemm_blocks) {
    __shared__ float Ws[FIN * D];
    __shared__ float As[20 * APAD];
    int tid = threadIdx.x;

    if (blockIdx.x >= gemm_blocks) {
        int e = (blockIdx.x - gemm_blocks) * 256 + tid;
        if (e < EE) {
            int c = load_idx(ei, (long long)EE + e, g_is64_edge);
            atomicAdd(&g_deg[c], ew[e]);
            atomicAdd(&g_cntn[c], 1);
        }
        return;
    }

    int row0 = blockIdx.x * 128;
    for (int i = tid; i < FIN * D; i += 256) Ws[i] = W[i];
    int tx = tid & 15, ty = tid >> 4;
    float acc[8][4] = {};

    for (int kb = 0; kb < FIN; kb += 20) {
        __syncthreads();  // also guards Ws on first iteration
        for (int i = tid; i < 128 * 20; i += 256) {
            int rr = i / 20, kk = i - rr * 20;
            int r = row0 + rr;
            As[kk * APAD + rr] = (r < NN) ? A[(long long)r * FIN + kb + kk] : 0.f;
        }
        __syncthreads();
#pragma unroll
        for (int k = 0; k < 20; k++) {
            float4 a0 = *(const float4*)&As[k * APAD + ty * 8];
            float4 a1 = *(const float4*)&As[k * APAD + ty * 8 + 4];
            float4 wv = *(const float4*)&Ws[(kb + k) * D + tx * 4];
            float av[8] = {a0.x, a0.y, a0.z, a0.w, a1.x, a1.y, a1.z, a1.w};
#pragma unroll
            for (int i2 = 0; i2 < 8; i2++) {
                acc[i2][0] += av[i2] * wv.x;
                acc[i2][1] += av[i2] * wv.y;
                acc[i2][2] += av[i2] * wv.z;
                acc[i2][3] += av[i2] * wv.w;
            }
        }
    }
    int c0 = tx * 4;
    float4 bc = *(const float4*)&biasC[c0];
#pragma unroll
    for (int i2 = 0; i2 < 8; i2++) {
        int r = row0 + ty * 8 + i2;
        if (r >= NN) break;
        float4 v = make_float4(fmaxf(acc[i2][0] + bc.x, 0.f), fmaxf(acc[i2][1] + bc.y, 0.f),
                               fmaxf(acc[i2][2] + bc.z, 0.f), fmaxf(acc[i2][3] + bc.w, 0.f));
        *(float4*)&C[(long long)r * D + c0] = v;
    }
}

// ---------------- two-level exclusive scan over g_cntn -> g_ptr --------------
__global__ void scan1_kernel() {
    __shared__ int sh[SCAN_T];
    int tid = threadIdx.x;
    int i = blockIdx.x * SCAN_T + tid;
    int v = (i < NN) ? g_cntn[i] : 0;
    sh[tid] = v;
    __syncthreads();
    for (int off = 1; off < SCAN_T; off <<= 1) {
        int t = (tid >= off) ? sh[tid - off] : 0;
        __syncthreads();
        sh[tid] += t;
        __syncthreads();
    }
    if (i < NN) g_ptr[i] = sh[tid] - v;  // exclusive (local)
    if (tid == SCAN_T - 1) g_partials[blockIdx.x] = sh[tid];
}

__global__ void scan2_kernel() {  // 1 block of 256 (SCAN_NB=196 < 256)
    __shared__ int sh[256];
    int tid = threadIdx.x;
    int v = (tid < SCAN_NB) ? g_partials[tid] : 0;
    sh[tid] = v;
    __syncthreads();
    for (int off = 1; off < 256; off <<= 1) {
        int t = (tid >= off) ? sh[tid - off] : 0;
        __syncthreads();
        sh[tid] += t;
        __syncthreads();
    }
    if (tid < SCAN_NB) g_partials[tid] = sh[tid] - v;  // exclusive
}

// ---------------- conv GEMM (fp32, R7 schedule, fp16 out) + optional scatter -
template <bool DO_SCATTER>
__global__ void gemm_conv(const float* __restrict__ A, const float* __restrict__ W,
                          unsigned* __restrict__ hout, int nrows,
                          const void* ei, const float* __restrict__ ew,
                          int gemm_blocks) {
    __shared__ float Ws[D * D];
    __shared__ float As[32 * APAD];

    int tid = threadIdx.x;
    if (DO_SCATTER && blockIdx.x >= gemm_blocks) {
        int e = (blockIdx.x - gemm_blocks) * 256 + tid;
        if (e < EE) {
            int is64 = g_is64_edge;
            int r = load_idx(ei, e, is64);
            int c = load_idx(ei, (long long)EE + e, is64);
            float dr = g_deg[r], dc = g_deg[c];
            float ir = dr > 0.f ? rsqrtf(dr) : 0.f;
            float ic = dc > 0.f ? rsqrtf(dc) : 0.f;
            int old = atomicSub(&g_cntn[c], 1);
            int p = ptr_of(c) + old - 1;
            g_csr[p] = make_int2(r, __float_as_int(ir * ew[e] * ic));
        }
        return;
    }

    int row0 = blockIdx.x * 128;
    for (int i = tid; i < D * D; i += 256) Ws[i] = W[i];
    int tx = tid & 15, ty = tid >> 4;
    float acc[8][4] = {};

    for (int kb = 0; kb < D; kb += 32) {
        __syncthreads();
        for (int i = tid; i < 128 * 32; i += 256) {
            int rr = i >> 5, kk = i & 31;
            int r = row0 + rr;
            As[kk * APAD + rr] = (r < nrows) ? A[(long long)r * D + kb + kk] : 0.f;
        }
        __syncthreads();
#pragma unroll
        for (int k = 0; k < 32; k++) {
            float4 a0 = *(const float4*)&As[k * APAD + ty * 8];
            float4 a1 = *(const float4*)&As[k * APAD + ty * 8 + 4];
            float4 wv = *(const float4*)&Ws[(kb + k) * D + tx * 4];
            float av[8] = {a0.x, a0.y, a0.z, a0.w, a1.x, a1.y, a1.z, a1.w};
#pragma unroll
            for (int i2 = 0; i2 < 8; i2++) {
                acc[i2][0] += av[i2] * wv.x;
                acc[i2][1] += av[i2] * wv.y;
                acc[i2][2] += av[i2] * wv.z;
                acc[i2][3] += av[i2] * wv.w;
            }
        }
    }

#pragma unroll
    for (int i2 = 0; i2 < 8; i2++) {
        int r = row0 + ty * 8 + i2;
        if (r >= nrows) break;
        __half2 ha = __floats2half2_rn(acc[i2][0], acc[i2][1]);
        __half2 hb = __floats2half2_rn(acc[i2][2], acc[i2][3]);
        uint2 u;
        u.x = *(unsigned*)&ha;
        u.y = *(unsigned*)&hb;
        ((uint2*)hout)[(long long)r * 16 + tx] = u;
    }
}

// ---------------- CSR aggregation core: 4x unrolled, 16 edges in flight ------
// One warp per node; q=lane>>3 in {0..3}, p=lane&7 covers the 128B fp16 row.
// Lane sequence i = s+q, s+q+4, ... ; 4 independent (csr, gather) pairs per
// iteration -> MLP 16 per warp.
__device__ __forceinline__ void agg_accum(float acc[8], uint4 u, float nv) {
    __half2* hh = (__half2*)&u;
#pragma unroll
    for (int c = 0; c < 4; c++) {
        float2 f = __half22float2(hh[c]);
        acc[2 * c]     += f.x * nv;
        acc[2 * c + 1] += f.y * nv;
    }
}

__device__ __forceinline__ void agg_core(int node, const uint4* __restrict__ h,
                                         int q, int p, float acc[8]) {
    int s = ptr_of(node), e = ptr_of(node + 1);
    int i = s + q;
    for (; i + 12 < e; i += 16) {
        int2 e0 = g_csr[i];
        int2 e1 = g_csr[i + 4];
        int2 e2 = g_csr[i + 8];
        int2 e3 = g_csr[i + 12];
        uint4 u0 = h[e0.x * 8 + p];
        uint4 u1 = h[e1.x * 8 + p];
        uint4 u2 = h[e2.x * 8 + p];
        uint4 u3 = h[e3.x * 8 + p];
        agg_accum(acc, u0, __int_as_float(e0.y));
        agg_accum(acc, u1, __int_as_float(e1.y));
        agg_accum(acc, u2, __int_as_float(e2.y));
        agg_accum(acc, u3, __int_as_float(e3.y));
    }
    if (i + 4 < e) {
        int2 e0 = g_csr[i];
        int2 e1 = g_csr[i + 4];
        uint4 u0 = h[e0.x * 8 + p];
        uint4 u1 = h[e1.x * 8 + p];
        agg_accum(acc, u0, __int_as_float(e0.y));
        agg_accum(acc, u1, __int_as_float(e1.y));
        i += 8;
    }
    if (i < e) {
        int2 e0 = g_csr[i];
        uint4 u0 = h[e0.x * 8 + p];
        agg_accum(acc, u0, __int_as_float(e0.y));
    }
#pragma unroll
    for (int c = 0; c < 8; c++) {
        acc[c] += __shfl_xor_sync(0xffffffffu, acc[c], 8);
        acc[c] += __shfl_xor_sync(0xffffffffu, acc[c], 16);
    }
}

__global__ void agg_half(const uint4* __restrict__ h,
                         const float* __restrict__ bias, float* __restrict__ outp) {
    int node = (blockIdx.x * blockDim.x + threadIdx.x) >> 5;
    if (node >= NN) return;
    int lane = threadIdx.x & 31;
    int q = lane >> 3, p = lane & 7;
    float acc[8] = {};
    agg_core(node, h, q, p, acc);
    if (q == 0) {
        float4 b0 = *(const float4*)&bias[8 * p];
        float4 b1 = *(const float4*)&bias[8 * p + 4];
        float4 o0 = make_float4(fmaxf(acc[0] + b0.x, 0.f), fmaxf(acc[1] + b0.y, 0.f),
                                fmaxf(acc[2] + b0.z, 0.f), fmaxf(acc[3] + b0.w, 0.f));
        float4 o1 = make_float4(fmaxf(acc[4] + b1.x, 0.f), fmaxf(acc[5] + b1.y, 0.f),
                                fmaxf(acc[6] + b1.z, 0.f), fmaxf(acc[7] + b1.w, 0.f));
        float* row = outp + (long long)node * D + 8 * p;
        *(float4*)row = o0;
        *(float4*)(row + 4) = o1;
    }
}

__device__ __forceinline__ void red_add_v4(float4* addr, float4 v) {
    asm volatile("red.global.add.v4.f32 [%0], {%1,%2,%3,%4};"
                 :: "l"(addr), "f"(v.x), "f"(v.y), "f"(v.z), "f"(v.w)
                 : "memory");
}

// Last layer: aggregate + bias + relu + mean-pool accumulate.
__global__ void agg_pool(const uint4* __restrict__ h,
                         const float* __restrict__ bias, const void* batch) {
    int node = (blockIdx.x * blockDim.x + threadIdx.x) >> 5;
    if (node >= NN) return;
    int lane = threadIdx.x & 31;
    int q = lane >> 3, p = lane & 7;
    float acc[8] = {};
    agg_core(node, h, q, p, acc);
    if (q == 0) {
        int g = load_idx(batch, node, g_is64_batch);
        float4 b0 = *(const float4*)&bias[8 * p];
        float4 b1 = *(const float4*)&bias[8 * p + 4];
        float4 o0 = make_float4(fmaxf(acc[0] + b0.x, 0.f), fmaxf(acc[1] + b0.y, 0.f),
                                fmaxf(acc[2] + b0.z, 0.f), fmaxf(acc[3] + b0.w, 0.f));
        float4 o1 = make_float4(fmaxf(acc[4] + b1.x, 0.f), fmaxf(acc[5] + b1.y, 0.f),
                                fmaxf(acc[6] + b1.z, 0.f), fmaxf(acc[7] + b1.w, 0.f));
        float* row = g_sums + g * D + 8 * p;
        red_add_v4((float4*)row, o0);
        red_add_v4((float4*)(row + 4), o1);
        if (p == 0) atomicAdd(&g_cnt[g], 1.0f);
    }
}

// ---------------- fused MLP tail: lin1 -> fc0 -> fc1 -> lin2 ----------------
__global__ void tail_kernel(const float* __restrict__ W1, const float* __restrict__ b1,
                            const float* __restrict__ fcw, const float* __restrict__ fcb,
                            const float* __restrict__ w2, const float* __restrict__ b2,
                            float* __restrict__ out) {
    int g = blockIdx.x, tid = threadIdx.x;  // 64 threads
    __shared__ float buf[2][64];
    __shared__ float red[64];

    buf[0][tid] = g_sums[g * D + tid] / fmaxf(g_cnt[g], 1.f);
    __syncthreads();
    {
        float acc = 0.f;
#pragma unroll
        for (int k = 0; k < 64; k++) acc += buf[0][k] * W1[k * D + tid];
        buf[1][tid] = fmaxf(acc + b1[tid], 0.f);
        __syncthreads();
    }
    int cur = 1;
    for (int L = 0; L < 2; L++) {
        const float* W = fcw + L * D * D;
        float acc = 0.f;
#pragma unroll
        for (int k = 0; k < 64; k++) acc += buf[cur][k] * W[k * D + tid];
        __syncthreads();
        buf[cur ^ 1][tid] = fmaxf(acc + fcb[L * D + tid], 0.f);
        cur ^= 1;
        __syncthreads();
    }
    red[tid] = buf[cur][tid] * w2[tid];
    __syncthreads();
    if (tid < 32) {
        float s = red[tid] + red[tid + 32];
#pragma unroll
        for (int off = 16; off; off >>= 1) s += __shfl_down_sync(0xffffffffu, s, off);
        if (tid == 0) out[g] = s + b2[0];
    }
}

// ---------------- launch ----------------
extern "C" void kernel_launch(void* const* d_in, const int* in_sizes, int n_in,
                              void* d_out, int out_size) {
    const float* x      = (const float*)d_in[0];
    const void*  ei     = d_in[1];
    const float* ew     = (const float*)d_in[2];
    const void*  batch  = d_in[3];
    const float* lin0_w = (const float*)d_in[4];
    const float* lin0_b = (const float*)d_in[5];
    const float* conv_w = (const float*)d_in[6];
    const float* conv_b = (const float*)d_in[7];
    const float* lin1_w = (const float*)d_in[8];
    const float* lin1_b = (const float*)d_in[9];
    const float* fc_w   = (const float*)d_in[10];
    const float* fc_b   = (const float*)d_in[11];
    const float* lin2_w = (const float*)d_in[12];
    const float* lin2_b = (const float*)d_in[13];
    float* out = (float*)d_out;

    float *p_out0, *p_aggA, *p_aggB;
    uint4* p_h;
    cudaGetSymbolAddress((void**)&p_out0, g_out0);
    cudaGetSymbolAddress((void**)&p_h,    g_hh);
    cudaGetSymbolAddress((void**)&p_aggA, g_aggA);
    cudaGetSymbolAddress((void**)&p_aggB, g_aggB);

    // init: zero deg/cntn/sums/cnt + dtype detect
    init_kernel<<<(NN + 255) / 256, 256>>>((const int*)ei, (const int*)batch);

    // fused lin0 GEMM + degree histogram (overlapped)
    const int GB = (NN + 127) / 128;           // 782 gemm blocks
    const int DB = (EE + 255) / 256;           // 6250 edge blocks
    fused_lin0_deg<<<GB + DB, 256>>>(x, lin0_w, lin0_b, p_out0, ei, ew, GB);

    scan1_kernel<<<SCAN_NB, SCAN_T>>>();
    scan2_kernel<<<1, 256>>>();

    float* bufs[2] = {p_aggA, p_aggB};
    const float* Ain = p_out0;
    const int AGB = (NN * 32) / 256;  // 12500 blocks
    for (int i = 0; i < 4; i++) {
        if (i == 0) {
            // conv-0 GEMM fused with CSR scatter (overlapped)
            gemm_conv<true><<<GB + DB, 256>>>(Ain, conv_w, (unsigned*)p_h, NN, ei, ew, GB);
        } else {
            gemm_conv<false><<<GB, 256>>>(Ain, conv_w + i * D * D, (unsigned*)p_h, NN,
                                          ei, ew, GB);
        }
        if (i < 3) {
            float* agg = bufs[i & 1];
            agg_half<<<AGB, 256>>>(p_h, conv_b + i * D, agg);
            Ain = agg;
        } else {
            agg_pool<<<AGB, 256>>>(p_h, conv_b + i * D, batch);
        }
    }

    tail_kernel<<<GG, 64>>>(lin1_w, lin1_b, fc_w, fc_b, lin2_w, lin2_b, out);
}